// round 1
// baseline (speedup 1.0000x reference)
#include <cuda_runtime.h>
#include <float.h>
#include <math.h>

// Problem constants
#define Bc   4
#define Tc   4096
#define DINc 1024
#define Hc   16
#define Dc   64
#define TCc  128            // t-chunk per block
#define NCc  (Tc / TCc)     // 32 chunks

#define SA_STRIDE 260       // padded stride for duplicated-A tile (bank-conflict relief, 16B-aligned reads)

// Scratch (allocation-free rule: __device__ globals)
__device__ float g_Sm[Bc * Hc * Tc];            // local-scan m
__device__ float g_Su[Bc * Hc * Tc];            // local-scan u
__device__ float g_Sw[Bc * Hc * Tc * Dc];       // local-scan w (64 MB)
__device__ float g_Pm[Bc * Hc * NCc];           // exclusive chunk prefix m
__device__ float g_Pu[Bc * Hc * NCc];
__device__ float g_Pw[Bc * Hc * NCc * Dc];

// ---------------------------------------------------------------------------
// Kernel 1: fused GEMM (kv = relu(A @ W)) + st = q.k + local chunk scan
// Block: 256 threads. Tile: 128 (t) x 128 (2*D) x K=1024, BK=16.
// Inner loop uses packed fma.rn.f32x2 (2 fp32 FMA / instr) — A stored duplicated.
// ---------------------------------------------------------------------------
__global__ __launch_bounds__(256, 2)
void k1_gemm_scan(const float* __restrict__ A,   // [B,T,DIN]
                  const float* __restrict__ W,   // [DIN,H,D,2]
                  const float* __restrict__ Q)   // [H,D]
{
    const int c = blockIdx.x;      // chunk
    const int h = blockIdx.y;      // head
    const int b = blockIdx.z;      // batch
    const int t0 = c * TCc;
    const int tid = threadIdx.x;

    // Union buffer: GEMM phase uses sA2(16 x 260) + sW(16 x 128) = 6208 floats
    // Post phase uses Vs(128 x 65) + stS(128) + stPart(128 x 16) = 10496 floats
    __shared__ __align__(16) float smem[10496];
    float* sA2 = smem;                 // duplicated A: sA2[k][2m]=sA2[k][2m+1]=A[m][k]
    float* sW  = smem + 16 * SA_STRIDE;

    const int tx = tid & 15;
    const int ty = tid >> 4;
    const int rb = ty << 3;            // row base (t within chunk), 0..120
    const int cb = tx << 3;            // col base (j = 2d+kk), 0..120

    // load-phase mappings
    const int arow = tid >> 2;             // 0..63
    const int ac4  = (tid & 3) << 2;       // 0,4,8,12
    const int wrow = tid >> 5;             // 0..7
    const int wc4  = (tid & 31) << 2;      // 0..124

    const float* Ab = A + ((size_t)b * Tc + t0) * DINc;
    const float* Wh = W + (size_t)h * (Dc * 2);   // row stride Hc*Dc*2 = 2048

    unsigned long long accp[8][4];
    #pragma unroll
    for (int i = 0; i < 8; ++i)
        #pragma unroll
        for (int j = 0; j < 4; ++j)
            accp[i][j] = 0ull;

    for (int k0 = 0; k0 < DINc; k0 += 16) {
        __syncthreads();
        // A tile -> duplicated transposed smem
        #pragma unroll
        for (int it = 0; it < 2; ++it) {
            int r = arow + it * 64;
            float4 av = *reinterpret_cast<const float4*>(Ab + (size_t)r * DINc + k0 + ac4);
            float vals[4] = {av.x, av.y, av.z, av.w};
            #pragma unroll
            for (int e = 0; e < 4; ++e) {
                float2 d2 = make_float2(vals[e], vals[e]);
                *reinterpret_cast<float2*>(sA2 + (ac4 + e) * SA_STRIDE + 2 * r) = d2;
            }
        }
        // W tile -> smem (row-major, coalesced)
        #pragma unroll
        for (int it = 0; it < 2; ++it) {
            int r = wrow + it * 8;
            float4 wv = *reinterpret_cast<const float4*>(Wh + (size_t)(k0 + r) * (Hc * Dc * 2) + wc4);
            *reinterpret_cast<float4*>(sW + r * 128 + wc4) = wv;
        }
        __syncthreads();

        #pragma unroll
        for (int kk = 0; kk < 16; ++kk) {
            const float* aBase = sA2 + kk * SA_STRIDE + 2 * rb;
            const float* bBase = sW + kk * 128 + cb;
            unsigned long long ap[8], bp[4];
            #pragma unroll
            for (int i2 = 0; i2 < 4; ++i2) {
                ulonglong2 t2 = *reinterpret_cast<const ulonglong2*>(aBase + i2 * 4);
                ap[2 * i2] = t2.x; ap[2 * i2 + 1] = t2.y;
            }
            {
                ulonglong2 t0v = *reinterpret_cast<const ulonglong2*>(bBase);
                ulonglong2 t1v = *reinterpret_cast<const ulonglong2*>(bBase + 4);
                bp[0] = t0v.x; bp[1] = t0v.y; bp[2] = t1v.x; bp[3] = t1v.y;
            }
            #pragma unroll
            for (int i = 0; i < 8; ++i)
                #pragma unroll
                for (int j = 0; j < 4; ++j)
                    asm("fma.rn.f32x2 %0, %1, %2, %0;"
                        : "+l"(accp[i][j]) : "l"(ap[i]), "l"(bp[j]));
        }
    }

    // ---------------- epilogue: relu, Vs, st partials ----------------
    __syncthreads();                       // done reading sA2/sW
    float* Vs     = smem;                  // [128][65]
    float* stS    = smem + 128 * 65;       // [128]
    float* stPart = smem + 128 * 65 + 128; // [128][16]

    const int d0 = cb >> 1;                // this thread's 4 d-values: d0..d0+3
    float qv[4];
    #pragma unroll
    for (int jp = 0; jp < 4; ++jp) qv[jp] = Q[h * Dc + d0 + jp];

    #pragma unroll
    for (int i = 0; i < 8; ++i) {
        int r = rb + i;
        float stp = 0.f;
        #pragma unroll
        for (int jp = 0; jp < 4; ++jp) {
            unsigned lo = (unsigned)(accp[i][jp] & 0xffffffffull);
            unsigned hi = (unsigned)(accp[i][jp] >> 32);
            float kk_ = fmaxf(__uint_as_float(lo), 0.f);   // k (even col)
            float vv_ = fmaxf(__uint_as_float(hi), 0.f);   // v (odd col)
            stp = fmaf(qv[jp], kk_, stp);
            Vs[r * 65 + d0 + jp] = vv_;
        }
        stPart[r * 16 + tx] = stp;
    }
    __syncthreads();

    // deterministic st reduction (fixed order)
    if (tid < 128) {
        float s = 0.f;
        #pragma unroll
        for (int x = 0; x < 16; ++x) s += stPart[tid * 16 + x];
        stS[tid] = s;
    }
    __syncthreads();

    // ---------------- sequential local scan over the chunk ----------------
    if (tid < Dc) {
        const int lane = tid;
        const size_t baseT = ((size_t)(b * Hc + h)) * Tc + t0;
        float m = -FLT_MAX, u = 0.f, w = 0.f;
        for (int t = 0; t < TCc; ++t) {
            float st = stS[t];
            float mn = fmaxf(m, st);
            float ea = __expf(m - mn);
            float eb = __expf(st - mn);
            u = u * ea + eb;                        // ub = 1
            w = fmaf(w, ea, Vs[t * 65 + lane] * eb);
            m = mn;
            g_Sw[(baseT + t) * Dc + lane] = w;
            if (lane == 0) { g_Sm[baseT + t] = m; g_Su[baseT + t] = u; }
        }
    }
}

// ---------------------------------------------------------------------------
// Kernel 2: exclusive prefix over chunk summaries per (b,h). 64 blocks x 64 thr.
// ---------------------------------------------------------------------------
__global__ void k2_prefix()
{
    const int bh = blockIdx.x;
    const int lane = threadIdx.x;
    const size_t baseT = (size_t)bh * Tc;
    const size_t baseC = (size_t)bh * NCc;

    float m = -FLT_MAX, u = 0.f, w = 0.f;
    for (int cI = 0; cI < NCc; ++cI) {
        g_Pw[(baseC + cI) * Dc + lane] = w;
        if (lane == 0) { g_Pm[baseC + cI] = m; g_Pu[baseC + cI] = u; }
        int t = cI * TCc + (TCc - 1);
        float sm = g_Sm[baseT + t];
        float su = g_Su[baseT + t];
        float sw = g_Sw[(baseT + t) * Dc + lane];
        float mn = fmaxf(m, sm);
        float ea = __expf(m - mn);
        float eb = __expf(sm - mn);
        u = u * ea + su * eb;
        w = fmaf(w, ea, sw * eb);
        m = mn;
    }
}

// ---------------------------------------------------------------------------
// Kernel 3: combine prefix + local, h = w/u, sum over heads, write output.
// 4096 blocks x 256 threads (4 t-rows x 64 lanes each).
// ---------------------------------------------------------------------------
__global__ __launch_bounds__(256)
void k3_final(float* __restrict__ out)
{
    const int lane = threadIdx.x & 63;
    const size_t rowG = (size_t)blockIdx.x * 4 + (threadIdx.x >> 6);  // over B*T
    const int b = (int)(rowG >> 12);     // T = 4096
    const int t = (int)(rowG & 4095);
    const int cI = t / TCc;

    float acc = 0.f;
    #pragma unroll
    for (int h = 0; h < Hc; ++h) {
        const size_t bh = (size_t)b * Hc + h;
        const size_t ci = bh * NCc + cI;
        const size_t ti = bh * Tc + t;
        float pm = g_Pm[ci], pu = g_Pu[ci];
        float pw = g_Pw[ci * Dc + lane];
        float lm = g_Sm[ti], lu = g_Su[ti];
        float lw = g_Sw[ti * Dc + lane];
        float mn = fmaxf(pm, lm);
        float ea = __expf(pm - mn);
        float eb = __expf(lm - mn);
        float u = pu * ea + lu * eb;
        float w = fmaf(pw, ea, lw * eb);
        acc += w / u;
    }
    out[rowG * Dc + lane] = acc;
}

// ---------------------------------------------------------------------------
extern "C" void kernel_launch(void* const* d_in, const int* in_sizes, int n_in,
                              void* d_out, int out_size)
{
    const float* A = nullptr;  // inputs
    const float* W = nullptr;  // kv_kernel
    const float* Q = nullptr;  // q_kernel
    for (int i = 0; i < n_in; ++i) {
        if      (in_sizes[i] == Bc * Tc * DINc)      A = (const float*)d_in[i];
        else if (in_sizes[i] == DINc * Hc * Dc * 2)  W = (const float*)d_in[i];
        else if (in_sizes[i] == Hc * Dc)             Q = (const float*)d_in[i];
    }
    float* out = (float*)d_out;

    dim3 g1(NCc, Hc, Bc);
    k1_gemm_scan<<<g1, 256>>>(A, W, Q);
    k2_prefix<<<Bc * Hc, Dc>>>();
    k3_final<<<(Bc * Tc) / 4, 256>>>(out);
}

// round 3
// speedup vs baseline: 1.6817x; 1.6817x over previous
#include <cuda_runtime.h>
#include <float.h>
#include <math.h>

// Problem constants
#define Bc   4
#define Tc   4096
#define DINc 1024
#define Hc   16
#define Dc   64
#define TCc  128            // t-chunk per block
#define NCc  (Tc / TCc)     // 32 chunks

#define SA_STRIDE 260       // padded stride for duplicated-A tile
#define BUF_FLOATS (16 * SA_STRIDE + 16 * 128)   // 6208 floats per stage

// Scratch (allocation-free rule: __device__ globals)
__device__ float g_Sm[Bc * Hc * Tc];            // local-scan m
__device__ float g_Su[Bc * Hc * Tc];            // local-scan u
__device__ float g_Sw[Bc * Hc * Tc * Dc];       // local-scan w (64 MB)
__device__ float g_Pm[Bc * Hc * NCc];           // exclusive chunk prefix m
__device__ float g_Pu[Bc * Hc * NCc];
__device__ float g_Pw[Bc * Hc * NCc * Dc];

// ---------------------------------------------------------------------------
// Kernel 1: fused GEMM (kv = relu(A @ W)) + st = q.k + local chunk scan.
// Register-staged, double-buffered mainloop: LDG(next) -> compute(cur) ->
// STS(next) -> one __syncthreads per K-step.
// ---------------------------------------------------------------------------
__global__ __launch_bounds__(256, 2)
void k1_gemm_scan(const float* __restrict__ A,   // [B,T,DIN]
                  const float* __restrict__ W,   // [DIN,H,D,2]
                  const float* __restrict__ Q)   // [H,D]
{
    const int c = blockIdx.x;      // chunk
    const int h = blockIdx.y;      // head
    const int b = blockIdx.z;      // batch
    const int t0 = c * TCc;
    const int tid = threadIdx.x;

    // Double-buffered GEMM stage: 2 * 6208 floats = 49664 B.
    // Epilogue union needs 10496 floats. max = 12416 floats.
    __shared__ __align__(16) float smem[2 * BUF_FLOATS];

    const int tx = tid & 15;
    const int ty = tid >> 4;
    const int rb = ty << 3;            // row base (t within chunk)
    const int cb = tx << 3;            // col base (j = 2d+kk)

    // load-phase mappings
    const int arow = tid >> 2;             // 0..63
    const int ac4  = (tid & 3) << 2;       // 0,4,8,12
    const int wrow = tid >> 5;             // 0..7
    const int wc4  = (tid & 31) << 2;      // 0..124

    const float* Ab = A + ((size_t)b * Tc + t0) * DINc;
    const float* Wh = W + (size_t)h * (Dc * 2);   // row stride Hc*Dc*2 = 2048

    unsigned long long accp[8][4];
    #pragma unroll
    for (int i = 0; i < 8; ++i)
        #pragma unroll
        for (int j = 0; j < 4; ++j)
            accp[i][j] = 0ull;

    float4 a_stage[2], w_stage[2];

    // ---- prologue: load k0=0 tile into regs, STS to buffer 0 ----
    #pragma unroll
    for (int it = 0; it < 2; ++it) {
        a_stage[it] = *reinterpret_cast<const float4*>(Ab + (size_t)(arow + it * 64) * DINc + ac4);
        w_stage[it] = *reinterpret_cast<const float4*>(Wh + (size_t)(wrow + it * 8) * (Hc * Dc * 2) + wc4);
    }
    {
        float* sA2 = smem;
        float* sW  = smem + 16 * SA_STRIDE;
        #pragma unroll
        for (int it = 0; it < 2; ++it) {
            int r = arow + it * 64;
            float vals[4] = {a_stage[it].x, a_stage[it].y, a_stage[it].z, a_stage[it].w};
            #pragma unroll
            for (int e = 0; e < 4; ++e)
                *reinterpret_cast<float2*>(sA2 + (ac4 + e) * SA_STRIDE + 2 * r) =
                    make_float2(vals[e], vals[e]);
            *reinterpret_cast<float4*>(sW + (wrow + it * 8) * 128 + wc4) = w_stage[it];
        }
    }
    __syncthreads();

    int cur = 0;
    for (int k0 = 16; k0 <= DINc; k0 += 16) {
        const bool more = (k0 < DINc);
        // ---- issue next tile's global loads (latency hidden by compute) ----
        if (more) {
            #pragma unroll
            for (int it = 0; it < 2; ++it) {
                a_stage[it] = *reinterpret_cast<const float4*>(Ab + (size_t)(arow + it * 64) * DINc + k0 + ac4);
                w_stage[it] = *reinterpret_cast<const float4*>(Wh + (size_t)(k0 + wrow + it * 8) * (Hc * Dc * 2) + wc4);
            }
        }

        // ---- compute on current buffer ----
        {
            const float* sA2 = smem + cur * BUF_FLOATS;
            const float* sW  = sA2 + 16 * SA_STRIDE;
            #pragma unroll
            for (int kk = 0; kk < 16; ++kk) {
                const float* aBase = sA2 + kk * SA_STRIDE + 2 * rb;
                const float* bBase = sW + kk * 128 + cb;
                unsigned long long ap[8], bp[4];
                #pragma unroll
                for (int i2 = 0; i2 < 4; ++i2) {
                    ulonglong2 t2 = *reinterpret_cast<const ulonglong2*>(aBase + i2 * 4);
                    ap[2 * i2] = t2.x; ap[2 * i2 + 1] = t2.y;
                }
                {
                    ulonglong2 t0v = *reinterpret_cast<const ulonglong2*>(bBase);
                    ulonglong2 t1v = *reinterpret_cast<const ulonglong2*>(bBase + 4);
                    bp[0] = t0v.x; bp[1] = t0v.y; bp[2] = t1v.x; bp[3] = t1v.y;
                }
                #pragma unroll
                for (int i = 0; i < 8; ++i)
                    #pragma unroll
                    for (int j = 0; j < 4; ++j)
                        asm("fma.rn.f32x2 %0, %1, %2, %0;"
                            : "+l"(accp[i][j]) : "l"(ap[i]), "l"(bp[j]));
            }
        }

        // ---- stage next tile into the other buffer; one sync per K-step ----
        if (more) {
            float* sA2n = smem + (cur ^ 1) * BUF_FLOATS;
            float* sWn  = sA2n + 16 * SA_STRIDE;
            #pragma unroll
            for (int it = 0; it < 2; ++it) {
                int r = arow + it * 64;
                float vals[4] = {a_stage[it].x, a_stage[it].y, a_stage[it].z, a_stage[it].w};
                #pragma unroll
                for (int e = 0; e < 4; ++e)
                    *reinterpret_cast<float2*>(sA2n + (ac4 + e) * SA_STRIDE + 2 * r) =
                        make_float2(vals[e], vals[e]);
                *reinterpret_cast<float4*>(sWn + (wrow + it * 8) * 128 + wc4) = w_stage[it];
            }
            __syncthreads();
            cur ^= 1;
        }
    }

    // ---------------- epilogue: relu, Vs, st partials ----------------
    __syncthreads();                       // done reading GEMM buffers
    float* Vs     = smem;                  // [128][65]
    float* stS    = smem + 128 * 65;       // [128]
    float* stPart = smem + 128 * 65 + 128; // [128][16]

    const int d0 = cb >> 1;                // this thread's 4 d-values
    float qv[4];
    #pragma unroll
    for (int jp = 0; jp < 4; ++jp) qv[jp] = Q[h * Dc + d0 + jp];

    #pragma unroll
    for (int i = 0; i < 8; ++i) {
        int r = rb + i;
        float stp = 0.f;
        #pragma unroll
        for (int jp = 0; jp < 4; ++jp) {
            unsigned lo = (unsigned)(accp[i][jp] & 0xffffffffull);
            unsigned hi = (unsigned)(accp[i][jp] >> 32);
            float kk_ = fmaxf(__uint_as_float(lo), 0.f);   // k (even col)
            float vv_ = fmaxf(__uint_as_float(hi), 0.f);   // v (odd col)
            stp = fmaf(qv[jp], kk_, stp);
            Vs[r * 65 + d0 + jp] = vv_;
        }
        stPart[r * 16 + tx] = stp;
    }
    __syncthreads();

    // deterministic st reduction (fixed order)
    if (tid < 128) {
        float s = 0.f;
        #pragma unroll
        for (int x = 0; x < 16; ++x) s += stPart[tid * 16 + x];
        stS[tid] = s;
    }
    __syncthreads();

    // ---------------- sequential local scan over the chunk ----------------
    if (tid < Dc) {
        const int lane = tid;
        const size_t baseT = ((size_t)(b * Hc + h)) * Tc + t0;
        float m = -FLT_MAX, u = 0.f, w = 0.f;
        for (int t = 0; t < TCc; ++t) {
            float st = stS[t];
            float mn = fmaxf(m, st);
            float ea = __expf(m - mn);
            float eb = __expf(st - mn);
            u = u * ea + eb;                        // ub = 1
            w = fmaf(w, ea, Vs[t * 65 + lane] * eb);
            m = mn;
            g_Sw[(baseT + t) * Dc + lane] = w;
            if (lane == 0) { g_Sm[baseT + t] = m; g_Su[baseT + t] = u; }
        }
    }
}

// ---------------------------------------------------------------------------
// Kernel 2: exclusive prefix over chunk summaries per (b,h). 64 blocks x 64 thr.
// ---------------------------------------------------------------------------
__global__ void k2_prefix()
{
    const int bh = blockIdx.x;
    const int lane = threadIdx.x;
    const size_t baseT = (size_t)bh * Tc;
    const size_t baseC = (size_t)bh * NCc;

    float m = -FLT_MAX, u = 0.f, w = 0.f;
    for (int cI = 0; cI < NCc; ++cI) {
        g_Pw[(baseC + cI) * Dc + lane] = w;
        if (lane == 0) { g_Pm[baseC + cI] = m; g_Pu[baseC + cI] = u; }
        int t = cI * TCc + (TCc - 1);
        float sm = g_Sm[baseT + t];
        float su = g_Su[baseT + t];
        float sw = g_Sw[(baseT + t) * Dc + lane];
        float mn = fmaxf(m, sm);
        float ea = __expf(m - mn);
        float eb = __expf(sm - mn);
        u = u * ea + su * eb;
        w = fmaf(w, ea, sw * eb);
        m = mn;
    }
}

// ---------------------------------------------------------------------------
// Kernel 3: combine prefix + local, h = w/u, sum over heads, write output.
// ---------------------------------------------------------------------------
__global__ __launch_bounds__(256)
void k3_final(float* __restrict__ out)
{
    const int lane = threadIdx.x & 63;
    const size_t rowG = (size_t)blockIdx.x * 4 + (threadIdx.x >> 6);  // over B*T
    const int b = (int)(rowG >> 12);     // T = 4096
    const int t = (int)(rowG & 4095);
    const int cI = t / TCc;

    float acc = 0.f;
    #pragma unroll
    for (int h = 0; h < Hc; ++h) {
        const size_t bh = (size_t)b * Hc + h;
        const size_t ci = bh * NCc + cI;
        const size_t ti = bh * Tc + t;
        float pm = g_Pm[ci], pu = g_Pu[ci];
        float pw = g_Pw[ci * Dc + lane];
        float lm = g_Sm[ti], lu = g_Su[ti];
        float lw = g_Sw[ti * Dc + lane];
        float mn = fmaxf(pm, lm);
        float ea = __expf(pm - mn);
        float eb = __expf(lm - mn);
        float u = pu * ea + lu * eb;
        float w = fmaf(pw, ea, lw * eb);
        acc += w / u;
    }
    out[rowG * Dc + lane] = acc;
}

// ---------------------------------------------------------------------------
extern "C" void kernel_launch(void* const* d_in, const int* in_sizes, int n_in,
                              void* d_out, int out_size)
{
    const float* A = nullptr;  // inputs
    const float* W = nullptr;  // kv_kernel
    const float* Q = nullptr;  // q_kernel
    for (int i = 0; i < n_in; ++i) {
        if      (in_sizes[i] == Bc * Tc * DINc)      A = (const float*)d_in[i];
        else if (in_sizes[i] == DINc * Hc * Dc * 2)  W = (const float*)d_in[i];
        else if (in_sizes[i] == Hc * Dc)             Q = (const float*)d_in[i];
    }
    float* out = (float*)d_out;

    dim3 g1(NCc, Hc, Bc);
    k1_gemm_scan<<<g1, 256>>>(A, W, Q);
    k2_prefix<<<Bc * Hc, Dc>>>();
    k3_final<<<(Bc * Tc) / 4, 256>>>(out);
}

// round 5
// speedup vs baseline: 1.9941x; 1.1857x over previous
#include <cuda_runtime.h>
#include <float.h>
#include <math.h>

// Problem constants
#define Bc   4
#define Tc   4096
#define DINc 1024
#define Hc   16
#define Dc   64
#define TCc  128            // t-chunk per block
#define NCc  (Tc / TCc)     // 32 chunks

#define SA_ST 132                         // padded stride for A tile [k][row]
#define STAGE_FLOATS (16 * SA_ST + 16 * 128)   // 4160 floats per stage

// Scratch (allocation-free rule: __device__ globals)
__device__ float g_Sm[Bc * Hc * Tc];            // local-scan m
__device__ float g_Su[Bc * Hc * Tc];            // local-scan u
__device__ float g_Sw[Bc * Hc * Tc * Dc];       // local-scan w (64 MB)
__device__ float g_Pm[Bc * Hc * NCc];           // exclusive chunk prefix m
__device__ float g_Pu[Bc * Hc * NCc];
__device__ float g_Pw[Bc * Hc * NCc * Dc];

// ---------------------------------------------------------------------------
// Kernel 1: fused GEMM (kv = relu(A @ W)) + st = q.k + local chunk scan.
// f32x2 accumulators packed by ROW-PAIRS: A operand is a natural bit-packed
// load of two consecutive rows from a plain transposed A tile (no smem dup);
// B operand duplicated in registers (ALU) instead of in shared memory.
// Per kk per thread: 4 LDS.128 (64 B) + 8 packs + 32 FFMA2.
// ---------------------------------------------------------------------------
__global__ __launch_bounds__(256, 2)
void k1_gemm_scan(const float* __restrict__ A,   // [B,T,DIN]
                  const float* __restrict__ W,   // [DIN,H,D,2]
                  const float* __restrict__ Q)   // [H,D]
{
    const int c = blockIdx.x;      // chunk
    const int h = blockIdx.y;      // head
    const int b = blockIdx.z;      // batch
    const int t0 = c * TCc;
    const int tid = threadIdx.x;

    // GEMM: 2 stages * 4160 floats = 8320. Epilogue union: 10496 floats (42KB).
    __shared__ __align__(16) float smem[10496];

    const int tx = tid & 15;
    const int ty = tid >> 4;
    const int rb = ty << 3;            // row base (t within chunk), 8 rows
    const int cb = tx << 3;            // col base (j = 2d+kk), 8 cols

    // load-phase mappings
    const int arow = tid >> 2;             // 0..63
    const int ac4  = (tid & 3) << 2;       // 0,4,8,12
    const int wrow = tid >> 5;             // 0..7
    const int wc4  = (tid & 31) << 2;      // 0..124

    const float* Ab = A + ((size_t)b * Tc + t0) * DINc;
    const float* Wh = W + (size_t)h * (Dc * 2);   // row stride Hc*Dc*2 = 2048

    // acc[p][j] = (c[rb+2p][cb+j], c[rb+2p+1][cb+j]) packed f32x2
    unsigned long long accp[4][8];
    #pragma unroll
    for (int p = 0; p < 4; ++p)
        #pragma unroll
        for (int j = 0; j < 8; ++j)
            accp[p][j] = 0ull;

    float4 a_stage[2], w_stage[2];

    // ---- prologue: load k0=0 tile into regs, STS to buffer 0 ----
    #pragma unroll
    for (int it = 0; it < 2; ++it) {
        a_stage[it] = *reinterpret_cast<const float4*>(Ab + (size_t)(arow + it * 64) * DINc + ac4);
        w_stage[it] = *reinterpret_cast<const float4*>(Wh + (size_t)(wrow + it * 8) * (Hc * Dc * 2) + wc4);
    }
    {
        float* sA = smem;
        float* sW = smem + 16 * SA_ST;
        #pragma unroll
        for (int it = 0; it < 2; ++it) {
            int r = arow + it * 64;
            float vals[4] = {a_stage[it].x, a_stage[it].y, a_stage[it].z, a_stage[it].w};
            #pragma unroll
            for (int e = 0; e < 4; ++e)
                sA[(ac4 + e) * SA_ST + r] = vals[e];        // transpose, no dup
            *reinterpret_cast<float4*>(sW + (wrow + it * 8) * 128 + wc4) = w_stage[it];
        }
    }
    __syncthreads();

    int cur = 0;
    for (int k0 = 16; k0 <= DINc; k0 += 16) {
        const bool more = (k0 < DINc);
        // ---- issue next tile's global loads (latency hidden by compute) ----
        if (more) {
            #pragma unroll
            for (int it = 0; it < 2; ++it) {
                a_stage[it] = *reinterpret_cast<const float4*>(Ab + (size_t)(arow + it * 64) * DINc + k0 + ac4);
                w_stage[it] = *reinterpret_cast<const float4*>(Wh + (size_t)(k0 + wrow + it * 8) * (Hc * Dc * 2) + wc4);
            }
        }

        // ---- compute on current buffer ----
        {
            const float* sA = smem + cur * STAGE_FLOATS;
            const float* sW = sA + 16 * SA_ST;
            #pragma unroll
            for (int kk = 0; kk < 16; ++kk) {
                // A: 8 consecutive rows -> 4 packed row-pairs (2x LDS.128)
                const float* aBase = sA + kk * SA_ST + rb;
                ulonglong2 a01 = *reinterpret_cast<const ulonglong2*>(aBase);
                ulonglong2 a23 = *reinterpret_cast<const ulonglong2*>(aBase + 4);
                unsigned long long ap[4] = {a01.x, a01.y, a23.x, a23.y};

                // B: 8 scalar cols (2x LDS.128), duplicated in registers
                const float* bBase = sW + kk * 128 + cb;
                float4 b0 = *reinterpret_cast<const float4*>(bBase);
                float4 b1 = *reinterpret_cast<const float4*>(bBase + 4);
                float bs[8] = {b0.x, b0.y, b0.z, b0.w, b1.x, b1.y, b1.z, b1.w};
                unsigned long long bp[8];
                #pragma unroll
                for (int j = 0; j < 8; ++j)
                    asm("mov.b64 %0, {%1, %1};"
                        : "=l"(bp[j]) : "r"(__float_as_uint(bs[j])));

                #pragma unroll
                for (int p = 0; p < 4; ++p)
                    #pragma unroll
                    for (int j = 0; j < 8; ++j)
                        asm("fma.rn.f32x2 %0, %1, %2, %0;"
                            : "+l"(accp[p][j]) : "l"(ap[p]), "l"(bp[j]));
            }
        }

        // ---- stage next tile into the other buffer; one sync per K-step ----
        if (more) {
            float* sAn = smem + (cur ^ 1) * STAGE_FLOATS;
            float* sWn = sAn + 16 * SA_ST;
            #pragma unroll
            for (int it = 0; it < 2; ++it) {
                int r = arow + it * 64;
                float vals[4] = {a_stage[it].x, a_stage[it].y, a_stage[it].z, a_stage[it].w};
                #pragma unroll
                for (int e = 0; e < 4; ++e)
                    sAn[(ac4 + e) * SA_ST + r] = vals[e];
                *reinterpret_cast<float4*>(sWn + (wrow + it * 8) * 128 + wc4) = w_stage[it];
            }
            __syncthreads();
            cur ^= 1;
        }
    }

    // ---------------- epilogue: relu, Vs, st partials ----------------
    __syncthreads();                       // done reading GEMM buffers
    float* Vs     = smem;                  // [128][65]
    float* stS    = smem + 128 * 65;       // [128]
    float* stPart = smem + 128 * 65 + 128; // [128][16]

    const int d0 = cb >> 1;                // this thread's 4 d-values
    float qv[4];
    #pragma unroll
    for (int jp = 0; jp < 4; ++jp) qv[jp] = Q[h * Dc + d0 + jp];

    #pragma unroll
    for (int p = 0; p < 4; ++p) {
        const int r0 = rb + 2 * p;
        float stp0 = 0.f, stp1 = 0.f;
        #pragma unroll
        for (int jp = 0; jp < 4; ++jp) {
            unsigned long long kk2 = accp[p][2 * jp];       // k column (even)
            unsigned long long vv2 = accp[p][2 * jp + 1];   // v column (odd)
            float k0_ = fmaxf(__uint_as_float((unsigned)(kk2 & 0xffffffffull)), 0.f);
            float k1_ = fmaxf(__uint_as_float((unsigned)(kk2 >> 32)), 0.f);
            float v0_ = fmaxf(__uint_as_float((unsigned)(vv2 & 0xffffffffull)), 0.f);
            float v1_ = fmaxf(__uint_as_float((unsigned)(vv2 >> 32)), 0.f);
            stp0 = fmaf(qv[jp], k0_, stp0);
            stp1 = fmaf(qv[jp], k1_, stp1);
            Vs[r0 * 65 + d0 + jp]       = v0_;
            Vs[(r0 + 1) * 65 + d0 + jp] = v1_;
        }
        stPart[r0 * 16 + tx]       = stp0;
        stPart[(r0 + 1) * 16 + tx] = stp1;
    }
    __syncthreads();

    // deterministic st reduction (fixed order)
    if (tid < 128) {
        float s = 0.f;
        #pragma unroll
        for (int x = 0; x < 16; ++x) s += stPart[tid * 16 + x];
        stS[tid] = s;
    }
    __syncthreads();

    // ---------------- sequential local scan over the chunk ----------------
    if (tid < Dc) {
        const int lane = tid;
        const size_t baseT = ((size_t)(b * Hc + h)) * Tc + t0;
        float m = -FLT_MAX, u = 0.f, w = 0.f;
        for (int t = 0; t < TCc; ++t) {
            float st = stS[t];
            float mn = fmaxf(m, st);
            float ea = __expf(m - mn);
            float eb = __expf(st - mn);
            u = u * ea + eb;                        // ub = 1
            w = fmaf(w, ea, Vs[t * 65 + lane] * eb);
            m = mn;
            g_Sw[(baseT + t) * Dc + lane] = w;
            if (lane == 0) { g_Sm[baseT + t] = m; g_Su[baseT + t] = u; }
        }
    }
}

// ---------------------------------------------------------------------------
// Kernel 2: exclusive prefix over chunk summaries per (b,h). 64 blocks x 64 thr.
// ---------------------------------------------------------------------------
__global__ void k2_prefix()
{
    const int bh = blockIdx.x;
    const int lane = threadIdx.x;
    const size_t baseT = (size_t)bh * Tc;
    const size_t baseC = (size_t)bh * NCc;

    float m = -FLT_MAX, u = 0.f, w = 0.f;
    for (int cI = 0; cI < NCc; ++cI) {
        g_Pw[(baseC + cI) * Dc + lane] = w;
        if (lane == 0) { g_Pm[baseC + cI] = m; g_Pu[baseC + cI] = u; }
        int t = cI * TCc + (TCc - 1);
        float sm = g_Sm[baseT + t];
        float su = g_Su[baseT + t];
        float sw = g_Sw[(baseT + t) * Dc + lane];
        float mn = fmaxf(m, sm);
        float ea = __expf(m - mn);
        float eb = __expf(sm - mn);
        u = u * ea + su * eb;
        w = fmaf(w, ea, sw * eb);
        m = mn;
    }
}

// ---------------------------------------------------------------------------
// Kernel 3: combine prefix + local, h = w/u, sum over heads, write output.
// ---------------------------------------------------------------------------
__global__ __launch_bounds__(256)
void k3_final(float* __restrict__ out)
{
    const int lane = threadIdx.x & 63;
    const size_t rowG = (size_t)blockIdx.x * 4 + (threadIdx.x >> 6);  // over B*T
    const int b = (int)(rowG >> 12);     // T = 4096
    const int t = (int)(rowG & 4095);
    const int cI = t / TCc;

    float acc = 0.f;
    #pragma unroll
    for (int h = 0; h < Hc; ++h) {
        const size_t bh = (size_t)b * Hc + h;
        const size_t ci = bh * NCc + cI;
        const size_t ti = bh * Tc + t;
        float pm = g_Pm[ci], pu = g_Pu[ci];
        float pw = g_Pw[ci * Dc + lane];
        float lm = g_Sm[ti], lu = g_Su[ti];
        float lw = g_Sw[ti * Dc + lane];
        float mn = fmaxf(pm, lm);
        float ea = __expf(pm - mn);
        float eb = __expf(lm - mn);
        float u = pu * ea + lu * eb;
        float w = fmaf(pw, ea, lw * eb);
        acc += w / u;
    }
    out[rowG * Dc + lane] = acc;
}

// ---------------------------------------------------------------------------
extern "C" void kernel_launch(void* const* d_in, const int* in_sizes, int n_in,
                              void* d_out, int out_size)
{
    const float* A = nullptr;  // inputs
    const float* W = nullptr;  // kv_kernel
    const float* Q = nullptr;  // q_kernel
    for (int i = 0; i < n_in; ++i) {
        if      (in_sizes[i] == Bc * Tc * DINc)      A = (const float*)d_in[i];
        else if (in_sizes[i] == DINc * Hc * Dc * 2)  W = (const float*)d_in[i];
        else if (in_sizes[i] == Hc * Dc)             Q = (const float*)d_in[i];
    }
    float* out = (float*)d_out;

    dim3 g1(NCc, Hc, Bc);
    k1_gemm_scan<<<g1, 256>>>(A, W, Q);
    k2_prefix<<<Bc * Hc, Dc>>>();
    k3_final<<<(Bc * Tc) / 4, 256>>>(out);
}

// round 8
// speedup vs baseline: 3.3185x; 1.6642x over previous
#include <cuda_runtime.h>
#include <cuda_bf16.h>
#include <float.h>
#include <math.h>
#include <stdint.h>

// Problem constants
#define Bc   4
#define Tc   4096
#define DINc 1024
#define Hc   16
#define Dc   64
#define TCc  128            // t-chunk (M) per block
#define NCc  (Tc / TCc)     // 32 chunks
#define KC   64             // K per stage
#define NST  (DINc / KC)    // 16 stages

// SMEM stage layout: 4 matrices of [128 rows][72 bf16] (144 B padded rows)
#define SP_B   144                         // padded row bytes
#define MAT_B  (128 * SP_B)                // 18432
#define A0_OFF 0
#define A1_OFF MAT_B
#define B0_OFF (2 * MAT_B)
#define B1_OFF (3 * MAT_B)
#define STG_B  (4 * MAT_B)                 // 73728
#define SMEM_DYN (1024 + 2 * STG_B)        // 148480

// Scratch (allocation-free rule: __device__ globals)
__device__ __nv_bfloat16 g_A0[Bc * Tc * DINc];    // inputs hi split [b*t][k]
__device__ __nv_bfloat16 g_A1[Bc * Tc * DINc];    // inputs lo split
__device__ __nv_bfloat16 g_W0[Hc * 128 * DINc];   // W hi split [h][n][k]
__device__ __nv_bfloat16 g_W1[Hc * 128 * DINc];   // W lo split
__device__ float g_Sm[Bc * Hc * Tc];
__device__ float g_Su[Bc * Hc * Tc];
__device__ float g_Sw[Bc * Hc * Tc * Dc];
__device__ float g_Pm[Bc * Hc * NCc];
__device__ float g_Pu[Bc * Hc * NCc];
__device__ float g_Pw[Bc * Hc * NCc * Dc];

// ---------------- PTX helpers (all baseline sm_80+ features) ----------------
__device__ __forceinline__ uint32_t smem_u32(const void* p) {
    uint32_t a;
    asm("{ .reg .u64 t; cvta.to.shared.u64 t, %1; cvt.u32.u64 %0, t; }" : "=r"(a) : "l"(p));
    return a;
}
__device__ __forceinline__ void cp16(uint32_t dst, const void* src) {
    asm volatile("cp.async.ca.shared.global [%0], [%1], 16;" :: "r"(dst), "l"(src));
}
#define CP_COMMIT() asm volatile("cp.async.commit_group;" ::: "memory")
#define CP_WAIT1()  asm volatile("cp.async.wait_group 1;" ::: "memory")
#define CP_WAIT0()  asm volatile("cp.async.wait_group 0;" ::: "memory")

#define LDSM4(r, addr) \
    asm volatile("ldmatrix.sync.aligned.m8n8.x4.shared.b16 {%0,%1,%2,%3}, [%4];" \
        : "=r"((r)[0]), "=r"((r)[1]), "=r"((r)[2]), "=r"((r)[3]) : "r"(addr))

#define MMA_BF16(d, a, b) \
    asm volatile("mma.sync.aligned.m16n8k16.row.col.f32.bf16.bf16.f32 " \
        "{%0,%1,%2,%3}, {%4,%5,%6,%7}, {%8,%9}, {%0,%1,%2,%3};" \
        : "+f"((d)[0]), "+f"((d)[1]), "+f"((d)[2]), "+f"((d)[3]) \
        : "r"((a)[0]), "r"((a)[1]), "r"((a)[2]), "r"((a)[3]), \
          "r"((b)[0]), "r"((b)[1]))

__device__ __forceinline__ unsigned bf2u(__nv_bfloat162 v) {
    return *reinterpret_cast<unsigned*>(&v);
}

// ---------------------------------------------------------------------------
// prep_A: split inputs fp32 -> bf16 hi/lo (same [b*t][k] layout).
// ---------------------------------------------------------------------------
__global__ __launch_bounds__(256)
void prep_A(const float* __restrict__ A)
{
    size_t i4 = ((size_t)blockIdx.x * 256 + threadIdx.x) * 4;
    float4 v = *reinterpret_cast<const float4*>(A + i4);
    float h0 = __bfloat162float(__float2bfloat16_rn(v.x));
    float h1 = __bfloat162float(__float2bfloat16_rn(v.y));
    float h2 = __bfloat162float(__float2bfloat16_rn(v.z));
    float h3 = __bfloat162float(__float2bfloat16_rn(v.w));
    uint2 hi, lo;
    hi.x = bf2u(__floats2bfloat162_rn(v.x, v.y));
    hi.y = bf2u(__floats2bfloat162_rn(v.z, v.w));
    lo.x = bf2u(__floats2bfloat162_rn(v.x - h0, v.y - h1));
    lo.y = bf2u(__floats2bfloat162_rn(v.z - h2, v.w - h3));
    *reinterpret_cast<uint2*>(reinterpret_cast<char*>(g_A0) + i4 * 2) = hi;
    *reinterpret_cast<uint2*>(reinterpret_cast<char*>(g_A1) + i4 * 2) = lo;
}

// ---------------------------------------------------------------------------
// prep_W: split W into bf16 hi/lo AND transpose to [h][n][k] K-major.
// ---------------------------------------------------------------------------
__global__ __launch_bounds__(256)
void prep_W(const float* __restrict__ W)
{
    int idx = blockIdx.x * 256 + threadIdx.x;    // 0..524287
    int jg  = idx & 31;
    int h   = (idx >> 5) & 15;
    int k   = idx >> 9;
    float4 w = *reinterpret_cast<const float4*>(W + (size_t)k * (Hc * Dc * 2) + h * 128 + jg * 4);
    float x[4] = {w.x, w.y, w.z, w.w};
    #pragma unroll
    for (int e = 0; e < 4; ++e) {
        __nv_bfloat16 hb = __float2bfloat16_rn(x[e]);
        float hf = __bfloat162float(hb);
        __nv_bfloat16 lb = __float2bfloat16_rn(x[e] - hf);
        size_t o = ((size_t)h * 128 + jg * 4 + e) * DINc + k;
        g_W0[o] = hb;
        g_W1[o] = lb;
    }
}

// ---------------------------------------------------------------------------
// Kernel 1: bf16x2-split HMMA GEMM (kv = relu(A@W)) + st=q.k + local scan.
// Per CTA: M=128, N=128, K=1024. 8 warps in 4x2 (M x N), warp tile 32x64.
// cp.async double-buffered stages of KC=64.
// ---------------------------------------------------------------------------
__global__ __launch_bounds__(256, 1)
void k1_gemm_scan(const float* __restrict__ Q)
{
    extern __shared__ __align__(1024) char dsm[];
    const int c = blockIdx.x, h = blockIdx.y, b = blockIdx.z;
    const int t0 = c * TCc;
    const int tid = threadIdx.x;
    const int wid = tid >> 5, lane = tid & 31;
    const int wm = wid >> 1;           // 0..3 (M groups of 32)
    const int wn = wid & 1;            // 0..1 (N groups of 64)
    const uint32_t sb = smem_u32(dsm);

    float* qS = (float*)(dsm + 32);
    if (tid < 64) qS[tid] = Q[h * Dc + tid];

    const __nv_bfloat16* Ab0 = g_A0 + ((size_t)b * Tc + t0) * DINc;
    const __nv_bfloat16* Ab1 = g_A1 + ((size_t)b * Tc + t0) * DINc;
    const __nv_bfloat16* Wb0 = g_W0 + (size_t)h * 128 * DINc;
    const __nv_bfloat16* Wb1 = g_W1 + (size_t)h * 128 * DINc;

    // per-thread cp.async mapping: 4 chunks of 16B per matrix
    const int id0 = tid * 4;

    float acc[2][8][4];
    #pragma unroll
    for (int mt = 0; mt < 2; ++mt)
        #pragma unroll
        for (int nt = 0; nt < 8; ++nt)
            #pragma unroll
            for (int e = 0; e < 4; ++e) acc[mt][nt][e] = 0.f;

    // ---- issue stage 0 ----
    {
        uint32_t stg = sb + 1024;
        #pragma unroll
        for (int q = 0; q < 4; ++q) {
            int id = id0 + q;
            int row = id >> 3, c16 = id & 7;
            uint32_t dst = stg + row * SP_B + c16 * 16;
            size_t so = (size_t)row * DINc + c16 * 8;
            cp16(dst + A0_OFF, Ab0 + so);
            cp16(dst + A1_OFF, Ab1 + so);
            cp16(dst + B0_OFF, Wb0 + so);
            cp16(dst + B1_OFF, Wb1 + so);
        }
        CP_COMMIT();
    }

    for (int i = 0; i < NST; ++i) {
        if (i + 1 < NST) {
            uint32_t stg = sb + 1024 + ((i + 1) & 1) * STG_B;
            const int k0 = (i + 1) * KC;
            #pragma unroll
            for (int q = 0; q < 4; ++q) {
                int id = id0 + q;
                int row = id >> 3, c16 = id & 7;
                uint32_t dst = stg + row * SP_B + c16 * 16;
                size_t so = (size_t)row * DINc + k0 + c16 * 8;
                cp16(dst + A0_OFF, Ab0 + so);
                cp16(dst + A1_OFF, Ab1 + so);
                cp16(dst + B0_OFF, Wb0 + so);
                cp16(dst + B1_OFF, Wb1 + so);
            }
            CP_COMMIT();
            CP_WAIT1();
        } else {
            CP_WAIT0();
        }
        __syncthreads();

        // ---- compute on buffer i&1 ----
        const uint32_t stg = sb + 1024 + (i & 1) * STG_B;
        #pragma unroll
        for (int ks = 0; ks < 4; ++ks) {
            uint32_t aH[2][4], aL[2][4];
            #pragma unroll
            for (int mt = 0; mt < 2; ++mt) {
                int row = wm * 32 + mt * 16 + (lane & 15);
                uint32_t ad = stg + A0_OFF + row * SP_B + (ks * 16 + (lane >> 4) * 8) * 2;
                LDSM4(aH[mt], ad);
                LDSM4(aL[mt], ad + (A1_OFF - A0_OFF));
            }
            uint32_t bH[8][2], bL[8][2];
            #pragma unroll
            for (int nt2 = 0; nt2 < 4; ++nt2) {
                int row = wn * 64 + nt2 * 16 + (lane & 7) + (lane >> 4) * 8;
                uint32_t bd = stg + B0_OFF + row * SP_B + (ks * 16 + ((lane >> 3) & 1) * 8) * 2;
                uint32_t r[4];
                LDSM4(r, bd);
                bH[2 * nt2][0] = r[0]; bH[2 * nt2][1] = r[1];
                bH[2 * nt2 + 1][0] = r[2]; bH[2 * nt2 + 1][1] = r[3];
                LDSM4(r, bd + (B1_OFF - B0_OFF));
                bL[2 * nt2][0] = r[0]; bL[2 * nt2][1] = r[1];
                bL[2 * nt2 + 1][0] = r[2]; bL[2 * nt2 + 1][1] = r[3];
            }
            #pragma unroll
            for (int mt = 0; mt < 2; ++mt)
                #pragma unroll
                for (int nt = 0; nt < 8; ++nt) {
                    MMA_BF16(acc[mt][nt], aH[mt], bH[nt]);
                    MMA_BF16(acc[mt][nt], aH[mt], bL[nt]);
                    MMA_BF16(acc[mt][nt], aL[mt], bH[nt]);
                }
        }
        __syncthreads();
    }

    // ---------------- epilogue: relu, st = q.k partials, Vs ----------------
    float* Vs     = (float*)(dsm + 1024);                    // [128][65]
    float* stS    = (float*)(dsm + 1024 + 128 * 65 * 4);     // [128]
    float* stPart = (float*)(dsm + 1024 + 128 * 65 * 4 + 512); // [128][8]

    const int g = lane >> 2;
    const int dq = lane & 3;
    #pragma unroll
    for (int mt = 0; mt < 2; ++mt) {
        const int m0 = wm * 32 + mt * 16 + g;
        float stp0 = 0.f, stp1 = 0.f;
        #pragma unroll
        for (int nt = 0; nt < 8; ++nt) {
            int d = wn * 32 + nt * 4 + dq;
            float qd = qS[d];
            float k0_ = fmaxf(acc[mt][nt][0], 0.f);
            float v0_ = fmaxf(acc[mt][nt][1], 0.f);
            float k1_ = fmaxf(acc[mt][nt][2], 0.f);
            float v1_ = fmaxf(acc[mt][nt][3], 0.f);
            stp0 = fmaf(qd, k0_, stp0);
            stp1 = fmaf(qd, k1_, stp1);
            Vs[m0 * 65 + d]       = v0_;
            Vs[(m0 + 8) * 65 + d] = v1_;
        }
        stPart[m0 * 8 + wn * 4 + dq]       = stp0;
        stPart[(m0 + 8) * 8 + wn * 4 + dq] = stp1;
    }
    __syncthreads();

    if (tid < 128) {
        float s = 0.f;
        #pragma unroll
        for (int x = 0; x < 8; ++x) s += stPart[tid * 8 + x];
        stS[tid] = s;
    }
    __syncthreads();

    // ---------------- sequential local scan over the chunk ----------------
    if (tid < Dc) {
        const int sl = tid;
        const size_t baseT = ((size_t)(b * Hc + h)) * Tc + t0;
        float m = -FLT_MAX, u = 0.f, w = 0.f;
        for (int t = 0; t < TCc; ++t) {
            float st = stS[t];
            float mn = fmaxf(m, st);
            float ea = __expf(m - mn);
            float eb = __expf(st - mn);
            u = u * ea + eb;
            w = fmaf(w, ea, Vs[t * 65 + sl] * eb);
            m = mn;
            g_Sw[(baseT + t) * Dc + sl] = w;
            if (sl == 0) { g_Sm[baseT + t] = m; g_Su[baseT + t] = u; }
        }
    }
}

// ---------------------------------------------------------------------------
// Kernel 2: exclusive prefix over chunk summaries per (b,h).
// ---------------------------------------------------------------------------
__global__ void k2_prefix()
{
    const int bh = blockIdx.x;
    const int lane = threadIdx.x;
    const size_t baseT = (size_t)bh * Tc;
    const size_t baseC = (size_t)bh * NCc;

    float m = -FLT_MAX, u = 0.f, w = 0.f;
    for (int cI = 0; cI < NCc; ++cI) {
        g_Pw[(baseC + cI) * Dc + lane] = w;
        if (lane == 0) { g_Pm[baseC + cI] = m; g_Pu[baseC + cI] = u; }
        int t = cI * TCc + (TCc - 1);
        float sm = g_Sm[baseT + t];
        float su = g_Su[baseT + t];
        float sw = g_Sw[(baseT + t) * Dc + lane];
        float mn = fmaxf(m, sm);
        float ea = __expf(m - mn);
        float eb = __expf(sm - mn);
        u = u * ea + su * eb;
        w = fmaf(w, ea, sw * eb);
        m = mn;
    }
}

// ---------------------------------------------------------------------------
// Kernel 3: combine prefix + local, h = w/u, sum over heads.
// ---------------------------------------------------------------------------
__global__ __launch_bounds__(256)
void k3_final(float* __restrict__ out)
{
    const int lane = threadIdx.x & 63;
    const size_t rowG = (size_t)blockIdx.x * 4 + (threadIdx.x >> 6);
    const int b = (int)(rowG >> 12);
    const int t = (int)(rowG & 4095);
    const int cI = t / TCc;

    float acc = 0.f;
    #pragma unroll
    for (int h = 0; h < Hc; ++h) {
        const size_t bh = (size_t)b * Hc + h;
        const size_t ci = bh * NCc + cI;
        const size_t ti = bh * Tc + t;
        float pm = g_Pm[ci], pu = g_Pu[ci];
        float pw = g_Pw[ci * Dc + lane];
        float lm = g_Sm[ti], lu = g_Su[ti];
        float lw = g_Sw[ti * Dc + lane];
        float mn = fmaxf(pm, lm);
        float ea = __expf(pm - mn);
        float eb = __expf(lm - mn);
        float u = pu * ea + lu * eb;
        float w = fmaf(pw, ea, lw * eb);
        acc += w / u;
    }
    out[rowG * Dc + lane] = acc;
}

// ---------------------------------------------------------------------------
extern "C" void kernel_launch(void* const* d_in, const int* in_sizes, int n_in,
                              void* d_out, int out_size)
{
    const float* A = nullptr;
    const float* W = nullptr;
    const float* Q = nullptr;
    for (int i = 0; i < n_in; ++i) {
        if      (in_sizes[i] == Bc * Tc * DINc)      A = (const float*)d_in[i];
        else if (in_sizes[i] == DINc * Hc * Dc * 2)  W = (const float*)d_in[i];
        else if (in_sizes[i] == Hc * Dc)             Q = (const float*)d_in[i];
    }
    float* out = (float*)d_out;

    cudaFuncSetAttribute(k1_gemm_scan, cudaFuncAttributeMaxDynamicSharedMemorySize, SMEM_DYN);

    prep_A<<<(Bc * Tc * DINc) / 1024, 256>>>(A);
    prep_W<<<2048, 256>>>(W);
    dim3 g1(NCc, Hc, Bc);
    k1_gemm_scan<<<g1, 256, SMEM_DYN>>>(Q);
    k2_prefix<<<Bc * Hc, Dc>>>();
    k3_final<<<(Bc * Tc) / 4, 256>>>(out);
}

// round 9
// speedup vs baseline: 4.1444x; 1.2489x over previous
#include <cuda_runtime.h>
#include <cuda_bf16.h>
#include <float.h>
#include <math.h>
#include <stdint.h>

// Problem constants
#define Bc   4
#define Tc   4096
#define DINc 1024
#define Hc   16
#define Dc   64
#define TCc  128            // t-chunk (M) per block
#define NCc  (Tc / TCc)     // 32 chunks
#define KC   32             // K per stage
#define NST  (DINc / KC)    // 32 stages

// SMEM stage: 4 matrices of [128 rows][32 bf16] (64 B rows, XOR-swizzled)
#define MAT_B  (128 * 64)                  // 8192
#define A0_OFF 0
#define A1_OFF MAT_B
#define B0_OFF (2 * MAT_B)
#define B1_OFF (3 * MAT_B)
#define STG_B  (4 * MAT_B)                 // 32768
#define NBUF   3
#define SMEM_DYN (1024 + NBUF * STG_B)     // 99328 -> 2 CTAs/SM

// Scratch (allocation-free rule: __device__ globals)
__device__ __nv_bfloat16 g_A0[Bc * Tc * DINc];    // inputs hi split [b*t][k]
__device__ __nv_bfloat16 g_A1[Bc * Tc * DINc];    // inputs lo split
__device__ __nv_bfloat16 g_W0[Hc * 128 * DINc];   // W hi split [h][n][k]
__device__ __nv_bfloat16 g_W1[Hc * 128 * DINc];   // W lo split
__device__ float g_Sm[Bc * Hc * Tc];
__device__ float g_Su[Bc * Hc * Tc];
__device__ float g_Sw[Bc * Hc * Tc * Dc];
__device__ float g_Pm[Bc * Hc * NCc];
__device__ float g_Pu[Bc * Hc * NCc];
__device__ float g_Pw[Bc * Hc * NCc * Dc];

// ---------------- PTX helpers (baseline sm_80+ features only) ----------------
__device__ __forceinline__ uint32_t smem_u32(const void* p) {
    uint32_t a;
    asm("{ .reg .u64 t; cvta.to.shared.u64 t, %1; cvt.u32.u64 %0, t; }" : "=r"(a) : "l"(p));
    return a;
}
__device__ __forceinline__ void cp16(uint32_t dst, const void* src) {
    asm volatile("cp.async.cg.shared.global [%0], [%1], 16;" :: "r"(dst), "l"(src));
}
#define CP_COMMIT() asm volatile("cp.async.commit_group;" ::: "memory")
#define CP_WAIT1()  asm volatile("cp.async.wait_group 1;" ::: "memory")
#define CP_WAIT0()  asm volatile("cp.async.wait_group 0;" ::: "memory")

#define LDSM4(r, addr) \
    asm volatile("ldmatrix.sync.aligned.m8n8.x4.shared.b16 {%0,%1,%2,%3}, [%4];" \
        : "=r"((r)[0]), "=r"((r)[1]), "=r"((r)[2]), "=r"((r)[3]) : "r"(addr))

#define MMA_BF16(d, a0, a1, a2, a3, b0, b1) \
    asm volatile("mma.sync.aligned.m16n8k16.row.col.f32.bf16.bf16.f32 " \
        "{%0,%1,%2,%3}, {%4,%5,%6,%7}, {%8,%9}, {%0,%1,%2,%3};" \
        : "+f"((d)[0]), "+f"((d)[1]), "+f"((d)[2]), "+f"((d)[3]) \
        : "r"(a0), "r"(a1), "r"(a2), "r"(a3), "r"(b0), "r"(b1))

__device__ __forceinline__ unsigned bf2u(__nv_bfloat162 v) {
    return *reinterpret_cast<unsigned*>(&v);
}
// XOR swizzle: byte offset of 16B chunk c in row r (64 B pitch)
__device__ __forceinline__ uint32_t swz(int row, int c) {
    return (uint32_t)(row * 64 + ((c ^ ((row >> 1) & 3)) << 4));
}

// ---------------------------------------------------------------------------
// prep: split inputs AND W into bf16 hi/lo. One launch for both.
// Blocks [0, 16384): A.   Blocks [16384, 18432): W (transposed to [h][n][k]).
// ---------------------------------------------------------------------------
__global__ __launch_bounds__(256)
void prep_split(const float* __restrict__ A, const float* __restrict__ W)
{
    if (blockIdx.x < 16384) {
        size_t i4 = ((size_t)blockIdx.x * 256 + threadIdx.x) * 4;
        float4 v = *reinterpret_cast<const float4*>(A + i4);
        float h0 = __bfloat162float(__float2bfloat16_rn(v.x));
        float h1 = __bfloat162float(__float2bfloat16_rn(v.y));
        float h2 = __bfloat162float(__float2bfloat16_rn(v.z));
        float h3 = __bfloat162float(__float2bfloat16_rn(v.w));
        uint2 hi, lo;
        hi.x = bf2u(__floats2bfloat162_rn(v.x, v.y));
        hi.y = bf2u(__floats2bfloat162_rn(v.z, v.w));
        lo.x = bf2u(__floats2bfloat162_rn(v.x - h0, v.y - h1));
        lo.y = bf2u(__floats2bfloat162_rn(v.z - h2, v.w - h3));
        *reinterpret_cast<uint2*>(reinterpret_cast<char*>(g_A0) + i4 * 2) = hi;
        *reinterpret_cast<uint2*>(reinterpret_cast<char*>(g_A1) + i4 * 2) = lo;
    } else {
        int idx = (blockIdx.x - 16384) * 256 + threadIdx.x;   // 0..524287
        int jg  = idx & 31;
        int h   = (idx >> 5) & 15;
        int k   = idx >> 9;
        float4 w = *reinterpret_cast<const float4*>(W + (size_t)k * (Hc * Dc * 2) + h * 128 + jg * 4);
        float x[4] = {w.x, w.y, w.z, w.w};
        #pragma unroll
        for (int e = 0; e < 4; ++e) {
            __nv_bfloat16 hb = __float2bfloat16_rn(x[e]);
            float hf = __bfloat162float(hb);
            __nv_bfloat16 lb = __float2bfloat16_rn(x[e] - hf);
            size_t o = ((size_t)h * 128 + jg * 4 + e) * DINc + k;
            g_W0[o] = hb;
            g_W1[o] = lb;
        }
    }
}

// ---------------------------------------------------------------------------
// Kernel 1: bf16x2-split HMMA GEMM (kv = relu(A@W)) + st=q.k + local scan.
// M=128, N=128, K=1024. 8 warps 4x2, warp tile 32x64. 3-stage cp.async
// pipeline, KC=32, XOR-swizzled 64B rows, 2 CTAs/SM.
// ---------------------------------------------------------------------------
__global__ __launch_bounds__(256, 2)
void k1_gemm_scan(const float* __restrict__ Q)
{
    extern __shared__ __align__(1024) char dsm[];
    const int c = blockIdx.x, h = blockIdx.y, b = blockIdx.z;
    const int t0 = c * TCc;
    const int tid = threadIdx.x;
    const int wid = tid >> 5, lane = tid & 31;
    const int wm = wid >> 1;           // 0..3 (M groups of 32)
    const int wn = wid & 1;            // 0..1 (N groups of 64)
    const uint32_t sb = smem_u32(dsm);

    float* qS = (float*)(dsm + 32);
    if (tid < 64) qS[tid] = Q[h * Dc + tid];

    const __nv_bfloat16* Ab0 = g_A0 + ((size_t)b * Tc + t0) * DINc;
    const __nv_bfloat16* Ab1 = g_A1 + ((size_t)b * Tc + t0) * DINc;
    const __nv_bfloat16* Wb0 = g_W0 + (size_t)h * 128 * DINc;
    const __nv_bfloat16* Wb1 = g_W1 + (size_t)h * 128 * DINc;

    // cp.async mapping: per matrix, thread does ids {2*tid, 2*tid+1}:
    // row = id>>2 (0..127), chunk c = id&3. Two chunks of one row per thread.
    const int ld_row = tid >> 1;                 // (2*tid)>>2
    const int ld_c0  = (tid & 1) * 2;            // 0 or 2

    float acc[2][8][4];
    #pragma unroll
    for (int mt = 0; mt < 2; ++mt)
        #pragma unroll
        for (int nt = 0; nt < 8; ++nt)
            #pragma unroll
            for (int e = 0; e < 4; ++e) acc[mt][nt][e] = 0.f;

    // helper lambda-ish macro to issue one stage's loads
    #define ISSUE_STAGE(SIDX)                                                     \
    do {                                                                          \
        uint32_t stg_ = sb + 1024 + ((SIDX) % NBUF) * STG_B;                      \
        const int k0_ = (SIDX) * KC;                                              \
        size_t so0 = (size_t)ld_row * DINc + k0_ + ld_c0 * 8;                     \
        uint32_t d0 = stg_ + swz(ld_row, ld_c0);                                  \
        uint32_t d1 = stg_ + swz(ld_row, ld_c0 + 1);                              \
        cp16(d0 + A0_OFF, Ab0 + so0);  cp16(d1 + A0_OFF, Ab0 + so0 + 8);          \
        cp16(d0 + A1_OFF, Ab1 + so0);  cp16(d1 + A1_OFF, Ab1 + so0 + 8);          \
        cp16(d0 + B0_OFF, Wb0 + so0);  cp16(d1 + B0_OFF, Wb0 + so0 + 8);          \
        cp16(d0 + B1_OFF, Wb1 + so0);  cp16(d1 + B1_OFF, Wb1 + so0 + 8);          \
        CP_COMMIT();                                                              \
    } while (0)

    ISSUE_STAGE(0);
    ISSUE_STAGE(1);

    for (int i = 0; i < NST; ++i) {
        if (i < NST - 1) CP_WAIT1(); else CP_WAIT0();
        __syncthreads();                 // all warps done with stage i-1's buffer
        if (i + 2 < NST) ISSUE_STAGE(i + 2);

        const uint32_t stg = sb + 1024 + (i % NBUF) * STG_B;
        #pragma unroll
        for (int ks = 0; ks < 2; ++ks) {
            uint32_t aH[2][4], aL[2][4];
            #pragma unroll
            for (int mt = 0; mt < 2; ++mt) {
                int row = wm * 32 + mt * 16 + (lane & 15);
                int cc = ks * 2 + (lane >> 4);
                uint32_t ad = stg + swz(row, cc);
                LDSM4(aH[mt], ad + A0_OFF);
                LDSM4(aL[mt], ad + A1_OFF);
            }
            #pragma unroll
            for (int nt2 = 0; nt2 < 4; ++nt2) {
                int row = wn * 64 + nt2 * 16 + (lane & 7) + ((lane >> 4) << 3);
                int cc = ks * 2 + ((lane >> 3) & 1);
                uint32_t bd = stg + swz(row, cc);
                uint32_t rH[4], rL[4];
                LDSM4(rH, bd + B0_OFF);
                LDSM4(rL, bd + B1_OFF);
                #pragma unroll
                for (int mt = 0; mt < 2; ++mt) {
                    float* d0 = acc[mt][2 * nt2];
                    float* d1 = acc[mt][2 * nt2 + 1];
                    MMA_BF16(d0, aH[mt][0], aH[mt][1], aH[mt][2], aH[mt][3], rH[0], rH[1]);
                    MMA_BF16(d0, aH[mt][0], aH[mt][1], aH[mt][2], aH[mt][3], rL[0], rL[1]);
                    MMA_BF16(d0, aL[mt][0], aL[mt][1], aL[mt][2], aL[mt][3], rH[0], rH[1]);
                    MMA_BF16(d1, aH[mt][0], aH[mt][1], aH[mt][2], aH[mt][3], rH[2], rH[3]);
                    MMA_BF16(d1, aH[mt][0], aH[mt][1], aH[mt][2], aH[mt][3], rL[2], rL[3]);
                    MMA_BF16(d1, aL[mt][0], aL[mt][1], aL[mt][2], aL[mt][3], rH[2], rH[3]);
                }
            }
        }
    }
    __syncthreads();                     // mainloop smem free before epilogue reuse

    // ---------------- epilogue: relu, st = q.k partials, Vs ----------------
    float* Vs     = (float*)(dsm + 1024);                      // [128][65]
    float* stS    = (float*)(dsm + 1024 + 128 * 65 * 4);       // [128]
    float* stPart = (float*)(dsm + 1024 + 128 * 65 * 4 + 512); // [128][8]

    const int g = lane >> 2;
    const int dq = lane & 3;
    #pragma unroll
    for (int mt = 0; mt < 2; ++mt) {
        const int m0 = wm * 32 + mt * 16 + g;
        float stp0 = 0.f, stp1 = 0.f;
        #pragma unroll
        for (int nt = 0; nt < 8; ++nt) {
            int d = wn * 32 + nt * 4 + dq;
            float qd = qS[d];
            float k0_ = fmaxf(acc[mt][nt][0], 0.f);
            float v0_ = fmaxf(acc[mt][nt][1], 0.f);
            float k1_ = fmaxf(acc[mt][nt][2], 0.f);
            float v1_ = fmaxf(acc[mt][nt][3], 0.f);
            stp0 = fmaf(qd, k0_, stp0);
            stp1 = fmaf(qd, k1_, stp1);
            Vs[m0 * 65 + d]       = v0_;
            Vs[(m0 + 8) * 65 + d] = v1_;
        }
        stPart[m0 * 8 + wn * 4 + dq]       = stp0;
        stPart[(m0 + 8) * 8 + wn * 4 + dq] = stp1;
    }
    __syncthreads();

    if (tid < 128) {
        float s = 0.f;
        #pragma unroll
        for (int x = 0; x < 8; ++x) s += stPart[tid * 8 + x];
        stS[tid] = s;
    }
    __syncthreads();

    // ---------------- sequential local scan over the chunk ----------------
    if (tid < Dc) {
        const int sl = tid;
        const size_t baseT = ((size_t)(b * Hc + h)) * Tc + t0;
        float m = -FLT_MAX, u = 0.f, w = 0.f;
        for (int t = 0; t < TCc; ++t) {
            float st = stS[t];
            float mn = fmaxf(m, st);
            float ea = __expf(m - mn);
            float eb = __expf(st - mn);
            u = u * ea + eb;
            w = fmaf(w, ea, Vs[t * 65 + sl] * eb);
            m = mn;
            g_Sw[(baseT + t) * Dc + sl] = w;
            if (sl == 0) { g_Sm[baseT + t] = m; g_Su[baseT + t] = u; }
        }
    }
}

// ---------------------------------------------------------------------------
// Kernel 2: exclusive prefix over chunk summaries per (b,h).
// Preload all 32 summaries with independent loads (MLP), then combine.
// ---------------------------------------------------------------------------
__global__ void k2_prefix()
{
    const int bh = blockIdx.x;
    const int lane = threadIdx.x;
    const size_t baseT = (size_t)bh * Tc;
    const size_t baseC = (size_t)bh * NCc;

    float sm[NCc], su[NCc], sw[NCc];
    #pragma unroll
    for (int cI = 0; cI < NCc; ++cI) {
        int t = cI * TCc + (TCc - 1);
        sm[cI] = g_Sm[baseT + t];
        su[cI] = g_Su[baseT + t];
        sw[cI] = g_Sw[(baseT + t) * Dc + lane];
    }
    float m = -FLT_MAX, u = 0.f, w = 0.f;
    #pragma unroll
    for (int cI = 0; cI < NCc; ++cI) {
        g_Pw[(baseC + cI) * Dc + lane] = w;
        if (lane == 0) { g_Pm[baseC + cI] = m; g_Pu[baseC + cI] = u; }
        float mn = fmaxf(m, sm[cI]);
        float ea = __expf(m - mn);
        float eb = __expf(sm[cI] - mn);
        u = u * ea + su[cI] * eb;
        w = fmaf(w, ea, sw[cI] * eb);
        m = mn;
    }
}

// ---------------------------------------------------------------------------
// Kernel 3: combine prefix + local, h = w/u, sum over heads.
// ---------------------------------------------------------------------------
__global__ __launch_bounds__(256)
void k3_final(float* __restrict__ out)
{
    const int lane = threadIdx.x & 63;
    const size_t rowG = (size_t)blockIdx.x * 4 + (threadIdx.x >> 6);
    const int b = (int)(rowG >> 12);
    const int t = (int)(rowG & 4095);
    const int cI = t / TCc;

    float acc = 0.f;
    #pragma unroll
    for (int h = 0; h < Hc; ++h) {
        const size_t bh = (size_t)b * Hc + h;
        const size_t ci = bh * NCc + cI;
        const size_t ti = bh * Tc + t;
        float pm = g_Pm[ci], pu = g_Pu[ci];
        float pw = g_Pw[ci * Dc + lane];
        float lm = g_Sm[ti], lu = g_Su[ti];
        float lw = g_Sw[ti * Dc + lane];
        float mn = fmaxf(pm, lm);
        float ea = __expf(pm - mn);
        float eb = __expf(lm - mn);
        float u = pu * ea + lu * eb;
        float w = fmaf(pw, ea, lw * eb);
        acc += w / u;
    }
    out[rowG * Dc + lane] = acc;
}

// ---------------------------------------------------------------------------
extern "C" void kernel_launch(void* const* d_in, const int* in_sizes, int n_in,
                              void* d_out, int out_size)
{
    const float* A = nullptr;
    const float* W = nullptr;
    const float* Q = nullptr;
    for (int i = 0; i < n_in; ++i) {
        if      (in_sizes[i] == Bc * Tc * DINc)      A = (const float*)d_in[i];
        else if (in_sizes[i] == DINc * Hc * Dc * 2)  W = (const float*)d_in[i];
        else if (in_sizes[i] == Hc * Dc)             Q = (const float*)d_in[i];
    }
    float* out = (float*)d_out;

    cudaFuncSetAttribute(k1_gemm_scan, cudaFuncAttributeMaxDynamicSharedMemorySize, SMEM_DYN);

    prep_split<<<16384 + 2048, 256>>>(A, W);
    dim3 g1(NCc, Hc, Bc);
    k1_gemm_scan<<<g1, 256, SMEM_DYN>>>(Q);
    k2_prefix<<<Bc * Hc, Dc>>>();
    k3_final<<<(Bc * Tc) / 4, 256>>>(out);
}